// round 2
// baseline (speedup 1.0000x reference)
#include <cuda_runtime.h>
#include <math.h>

// ---------------------------------------------------------------------------
// MegatronAttention: B=2, S=2048, H=2048, NH=16, DH=128
// Reference quirk: einsum 'bhqk,bhkd->bhkd' sums over q -> output is
// v[b,h,k,d] * colsum[b,h,k] with colsum = sum_q softmax(scores)[...,q,k].
// Pipeline:
//   1) qkv   = x @ w_qkv                      (4096x2048 @ 2048x6144)
//   2) s     = (Q @ K^T) / sqrt(128)          (32 batched 2048x2048x128, NT)
//   3) rowmax/rowinv per (bh,q)
//   4) colsum[bh,k] = sum_q exp(s-m)*inv
//   5) vals[b,s,h*128+d] = v * colsum
//   6) out   = vals @ w_o                     (4096x2048 @ 2048x2048)
// ---------------------------------------------------------------------------

#define BS_ 2
#define SEQ 2048
#define HD 2048
#define NH 16
#define DH 128
#define M_ROWS (BS_*SEQ)            // 4096
#define QKV_N (3*NH*DH)             // 6144
#define NBH (BS_*NH)                // 32

__device__ float g_qkv[(size_t)M_ROWS * QKV_N];                  // 100 MB
__device__ float g_scores[(size_t)NBH * SEQ * SEQ];              // 512 MB
__device__ float g_vals[(size_t)M_ROWS * HD];                    // 32 MB
__device__ float g_rowmax[NBH * SEQ];
__device__ float g_rowinv[NBH * SEQ];
__device__ float g_colsum[NBH * SEQ];

// ---------------------------------------------------------------------------
// Tiled SGEMM: C = alpha * A * op(B).  BM=BN=128, BK=8, 256 thr, 8x8/thread.
// TRANSB=0: B is [K,N] row-major.  TRANSB=1: B is [N,K] row-major (NT gemm).
// Batched via blockIdx.z with split offsets: off = (z/zdiv)*so + (z%zdiv)*si.
// All problem dims divide tile dims exactly (checked host-side constants).
// ---------------------------------------------------------------------------
#define BM 128
#define BN 128
#define BK 8
#define TM 8
#define TN 8

template <int TRANSB>
__global__ __launch_bounds__(256)
void sgemm_kernel(const float* __restrict__ A, const float* __restrict__ B,
                  float* __restrict__ C,
                  int M, int N, int K,
                  int lda, int ldb, int ldc,
                  int zdiv,
                  long long sAo, long long sAi,
                  long long sBo, long long sBi,
                  long long sCo, long long sCi,
                  float alpha)
{
    __shared__ float As[BK][BM];
    __shared__ float Bs[BK][BN];

    const int bz = blockIdx.z;
    const int zo = bz / zdiv, zi = bz % zdiv;
    A += zo * sAo + zi * sAi;
    B += zo * sBo + zi * sBi;
    C += zo * sCo + zi * sCi;

    const int m0 = blockIdx.y * BM;
    const int n0 = blockIdx.x * BN;
    const int tid = threadIdx.x;
    const int tx = tid & 15;      // 0..15
    const int ty = tid >> 4;      // 0..15

    // A tile loader: 128 rows x 8 cols = 256 float4 (2 per row)
    const int arow = tid >> 1;
    const int acol = (tid & 1) * 4;
    // B tile loader
    int brow, bcol;
    if (TRANSB) { brow = tid >> 1; bcol = (tid & 1) * 4; }       // [128 n][8 k]
    else        { brow = tid >> 5; bcol = (tid & 31) * 4; }      // [8 k][128 n]

    float acc[TM][TN];
#pragma unroll
    for (int i = 0; i < TM; i++)
#pragma unroll
        for (int j = 0; j < TN; j++) acc[i][j] = 0.f;

    for (int k0 = 0; k0 < K; k0 += BK) {
        float4 av = *reinterpret_cast<const float4*>(
            A + (long long)(m0 + arow) * lda + (k0 + acol));
        As[acol + 0][arow] = av.x;
        As[acol + 1][arow] = av.y;
        As[acol + 2][arow] = av.z;
        As[acol + 3][arow] = av.w;

        if (TRANSB) {
            float4 bv = *reinterpret_cast<const float4*>(
                B + (long long)(n0 + brow) * ldb + (k0 + bcol));
            Bs[bcol + 0][brow] = bv.x;
            Bs[bcol + 1][brow] = bv.y;
            Bs[bcol + 2][brow] = bv.z;
            Bs[bcol + 3][brow] = bv.w;
        } else {
            float4 bv = *reinterpret_cast<const float4*>(
                B + (long long)(k0 + brow) * ldb + (n0 + bcol));
            *reinterpret_cast<float4*>(&Bs[brow][bcol]) = bv;
        }
        __syncthreads();

#pragma unroll
        for (int kk = 0; kk < BK; kk++) {
            float a[TM], b[TN];
#pragma unroll
            for (int i = 0; i < TM; i++) a[i] = As[kk][ty * TM + i];
#pragma unroll
            for (int j = 0; j < TN; j++) b[j] = Bs[kk][tx * TN + j];
#pragma unroll
            for (int i = 0; i < TM; i++)
#pragma unroll
                for (int j = 0; j < TN; j++)
                    acc[i][j] += a[i] * b[j];
        }
        __syncthreads();
    }

#pragma unroll
    for (int i = 0; i < TM; i++) {
        const long long m = m0 + ty * TM + i;
#pragma unroll
        for (int j = 0; j < TN; j += 4) {
            float4 v;
            v.x = acc[i][j + 0] * alpha;
            v.y = acc[i][j + 1] * alpha;
            v.z = acc[i][j + 2] * alpha;
            v.w = acc[i][j + 3] * alpha;
            *reinterpret_cast<float4*>(C + m * ldc + n0 + tx * TN + j) = v;
        }
    }
}

// ---------------------------------------------------------------------------
// Per-row softmax stats: rowmax and 1/sum(exp(row - rowmax)), row length 2048.
// One block (256 thr) per row; each thread holds 8 values in registers.
// ---------------------------------------------------------------------------
__global__ __launch_bounds__(256)
void softmax_stats_kernel(const float* __restrict__ S,
                          float* __restrict__ rowmax,
                          float* __restrict__ rowinv)
{
    const long long row = blockIdx.x;
    const float* p = S + row * SEQ;
    const int tid = threadIdx.x;

    float v[8];
    float m = -1e30f;
#pragma unroll
    for (int i = 0; i < 8; i++) {
        v[i] = p[tid + 256 * i];
        m = fmaxf(m, v[i]);
    }
#pragma unroll
    for (int o = 16; o; o >>= 1) m = fmaxf(m, __shfl_xor_sync(0xffffffffu, m, o));

    __shared__ float sm[8];
    __shared__ float ssum[8];
    if ((tid & 31) == 0) sm[tid >> 5] = m;
    __syncthreads();
    float bm = fmaxf(fmaxf(fmaxf(sm[0], sm[1]), fmaxf(sm[2], sm[3])),
                     fmaxf(fmaxf(sm[4], sm[5]), fmaxf(sm[6], sm[7])));

    float s = 0.f;
#pragma unroll
    for (int i = 0; i < 8; i++) s += __expf(v[i] - bm);
#pragma unroll
    for (int o = 16; o; o >>= 1) s += __shfl_xor_sync(0xffffffffu, s, o);
    if ((tid & 31) == 0) ssum[tid >> 5] = s;
    __syncthreads();
    if (tid == 0) {
        float tot = ssum[0] + ssum[1] + ssum[2] + ssum[3] +
                    ssum[4] + ssum[5] + ssum[6] + ssum[7];
        rowmax[row] = bm;
        rowinv[row] = 1.0f / tot;
    }
}

// ---------------------------------------------------------------------------
// colsum[bh,k] = sum_q exp(S[bh,q,k] - rowmax[bh,q]) * rowinv[bh,q]
// grid (SEQ/256, NBH); coalesced: fixed q, threads read contiguous k chunk.
// ---------------------------------------------------------------------------
__global__ __launch_bounds__(256)
void colsum_kernel(const float* __restrict__ S,
                   const float* __restrict__ rowmax,
                   const float* __restrict__ rowinv,
                   float* __restrict__ colsum)
{
    const int bh = blockIdx.y;
    const int k = blockIdx.x * 256 + threadIdx.x;
    const float* sp = S + (long long)bh * SEQ * SEQ + k;
    const float* mp = rowmax + bh * SEQ;
    const float* ip = rowinv + bh * SEQ;

    float acc = 0.f;
#pragma unroll 4
    for (int q = 0; q < SEQ; q++)
        acc += __expf(sp[(long long)q * SEQ] - __ldg(&mp[q])) * __ldg(&ip[q]);
    colsum[bh * SEQ + k] = acc;
}

// ---------------------------------------------------------------------------
// vals[(b*S+s)*2048 + h*128 + d] = qkv[(b*S+s)*6144 + 4096 + h*128 + d]
//                                  * colsum[(b*16+h)*2048 + s]
// ---------------------------------------------------------------------------
__global__ __launch_bounds__(256)
void scale_v_kernel(const float* __restrict__ qkv,
                    const float* __restrict__ colsum,
                    float* __restrict__ vals)
{
    const long long idx = (long long)blockIdx.x * 256 + threadIdx.x; // < 4096*2048
    const int col = (int)(idx & (HD - 1));        // h*128+d
    const int row = (int)(idx >> 11);             // b*S+s
    const int h = col >> 7;
    const int b = row >> 11;
    const int s = row & (SEQ - 1);
    float cs = colsum[(b * NH + h) * SEQ + s];
    vals[idx] = qkv[(long long)row * QKV_N + (2 * NH * DH) + col] * cs;
}

// ---------------------------------------------------------------------------
extern "C" void kernel_launch(void* const* d_in, const int* in_sizes, int n_in,
                              void* d_out, int out_size)
{
    const float* x     = (const float*)d_in[0];
    const float* w_qkv = (const float*)d_in[1];
    const float* w_o   = (const float*)d_in[2];
    float* out = (float*)d_out;

    float *qkv, *scores, *vals, *rowmax, *rowinv, *colsum;
    cudaGetSymbolAddress((void**)&qkv,    g_qkv);
    cudaGetSymbolAddress((void**)&scores, g_scores);
    cudaGetSymbolAddress((void**)&vals,   g_vals);
    cudaGetSymbolAddress((void**)&rowmax, g_rowmax);
    cudaGetSymbolAddress((void**)&rowinv, g_rowinv);
    cudaGetSymbolAddress((void**)&colsum, g_colsum);

    // 1) qkv = x @ w_qkv : [4096,2048]x[2048,6144]
    sgemm_kernel<0><<<dim3(QKV_N / BN, M_ROWS / BM, 1), 256>>>(
        x, w_qkv, qkv, M_ROWS, QKV_N, HD,
        HD, QKV_N, QKV_N,
        1, 0, 0, 0, 0, 0, 0, 1.0f);

    // 2) scores = (Q @ K^T)/sqrt(128), batched over bh = b*16+h (z)
    const long long bstride = (long long)SEQ * QKV_N;   // per-batch in qkv
    const long long cstride = (long long)SEQ * SEQ;     // per-bh in scores
    sgemm_kernel<1><<<dim3(SEQ / BN, SEQ / BM, NBH), 256>>>(
        qkv,                 /* Q at c=0 */
        qkv + NH * DH,       /* K at c=1 */
        scores,
        SEQ, SEQ, DH,
        QKV_N, QKV_N, SEQ,
        NH,
        bstride, DH,         /* A: batch stride, head stride */
        bstride, DH,         /* B: same */
        NH * cstride, cstride,
        0.08838834764831845f /* 1/sqrt(128) */);

    // 3) per-row softmax stats
    softmax_stats_kernel<<<NBH * SEQ, 256>>>(scores, rowmax, rowinv);

    // 4) colsum over q
    colsum_kernel<<<dim3(SEQ / 256, NBH), 256>>>(scores, rowmax, rowinv, colsum);

    // 5) vals = v * colsum
    scale_v_kernel<<<(M_ROWS * HD) / 256, 256>>>(qkv, colsum, vals);

    // 6) out = vals @ w_o : [4096,2048]x[2048,2048]
    sgemm_kernel<0><<<dim3(HD / BN, M_ROWS / BM, 1), 256>>>(
        vals, w_o, out, M_ROWS, HD, HD,
        HD, HD, HD,
        1, 0, 0, 0, 0, 0, 0, 1.0f);
}

// round 4
// speedup vs baseline: 2.0738x; 2.0738x over previous
#include <cuda_runtime.h>
#include <cuda_bf16.h>
#include <math.h>

// ---------------------------------------------------------------------------
// MegatronAttention B=2,S=2048,H=2048,NH=16,DH=128 — mma.sync bf16x3-split GEMMs
// (tcgen05 unavailable: harness PTX target is sm_103 without 'a' features)
// out quirk: einsum 'bhqk,bhkd->bhkd' sums q -> out = v * colsum(softmax).
// ---------------------------------------------------------------------------
#define SEQ 2048
#define HDIM 2048
#define NH 16
#define DHEAD 128
#define MR 4096               // B*S
#define QN 6144               // 3*NH*DH
#define NBH 32

typedef long long ll;
typedef unsigned int u32;

// --------------------------- scratch buffers -------------------------------
__device__ __nv_bfloat16 g_xhi[(size_t)MR*HDIM], g_xlo[(size_t)MR*HDIM];
__device__ __nv_bfloat16 g_wqT_hi[(size_t)QN*HDIM], g_wqT_lo[(size_t)QN*HDIM];
__device__ __nv_bfloat16 g_woT_hi[(size_t)HDIM*HDIM], g_woT_lo[(size_t)HDIM*HDIM];
__device__ __nv_bfloat16 g_qkv_hi[(size_t)MR*QN], g_qkv_lo[(size_t)MR*QN];
__device__ float g_scores[(size_t)NBH*SEQ*SEQ];
__device__ __nv_bfloat16 g_vhi[(size_t)MR*HDIM], g_vlo[(size_t)MR*HDIM];
__device__ float g_rowmax[NBH*SEQ], g_rowinv[NBH*SEQ], g_colsum[NBH*SEQ];

// --------------------------- helpers ---------------------------------------
__device__ __forceinline__ u32 s2u(const void* p){
    u32 a; asm("{ .reg .u64 t; cvta.to.shared.u64 t, %1; cvt.u32.u64 %0, t; }":"=r"(a):"l"(p)); return a;
}
#define SWZ(o) ((o) ^ (((o)>>3)&0x70))

__device__ __forceinline__ void cpa16(u32 d, const void* s){
    asm volatile("cp.async.cg.shared.global [%0], [%1], 16;" :: "r"(d), "l"(s));
}
__device__ __forceinline__ void cpc(){ asm volatile("cp.async.commit_group;"); }
template<int N> __device__ __forceinline__ void cpw(){ asm volatile("cp.async.wait_group %0;"::"n"(N)); }

__device__ __forceinline__ void ldm4(u32* r, u32 addr){
    asm volatile("ldmatrix.sync.aligned.m8n8.x4.shared.b16 {%0,%1,%2,%3}, [%4];"
        : "=r"(r[0]),"=r"(r[1]),"=r"(r[2]),"=r"(r[3]) : "r"(addr));
}
__device__ __forceinline__ void mma16816(float* d, const u32* a, u32 b0, u32 b1){
    asm volatile("mma.sync.aligned.m16n8k16.row.col.f32.bf16.bf16.f32 "
        "{%0,%1,%2,%3}, {%4,%5,%6,%7}, {%8,%9}, {%0,%1,%2,%3};"
        : "+f"(d[0]),"+f"(d[1]),"+f"(d[2]),"+f"(d[3])
        : "r"(a[0]),"r"(a[1]),"r"(a[2]),"r"(a[3]), "r"(b0),"r"(b1));
}
__device__ __forceinline__ void bsplit(float v, __nv_bfloat16& h, __nv_bfloat16& l){
    h = __float2bfloat16(v);
    l = __float2bfloat16(v - __bfloat162float(h));
}

// --------------------------- mma.sync GEMM ---------------------------------
// C[M,N] = alpha * sum_k A[m,k]*B[n,k] (both row-major, k contiguous; "NT").
// A/B pre-split bf16 hi/lo; 3-term product. Tile 128x128, BK=64, 3 stages.
#define PIPE 3
#define KC 64
#define TILE_BYTES 16384          // 128 rows x 128B (64 bf16)
#define STAGE_BYTES (4*TILE_BYTES)
#define GSMEM_SZ (1024 + PIPE*STAGE_BYTES)

template<int EPI>   // 0 = f32 out, 1 = split bf16 hi/lo out
__global__ __launch_bounds__(256, 1)
void gemm_mma(const __nv_bfloat16* __restrict__ Ahi, const __nv_bfloat16* __restrict__ Alo,
              const __nv_bfloat16* __restrict__ Bhi, const __nv_bfloat16* __restrict__ Blo,
              float* __restrict__ Cf, __nv_bfloat16* __restrict__ Chi, __nv_bfloat16* __restrict__ Clo,
              int K, int lda, int ldb, int ldc, int zdiv,
              ll sAo, ll sAi, ll sBo, ll sBi, ll sCo, ll sCi, float alpha)
{
    extern __shared__ char smem[];
    const u32 stage0 = (s2u(smem) + 1023u) & ~1023u;
    const int tid = threadIdx.x;
    const int lane = tid & 31;
    const int wid = tid >> 5;
    const int wm = (wid & 1) * 64;          // warp M offset in tile
    const int wn = (wid >> 1) * 32;         // warp N offset in tile
    const int lrow16 = lane & 15;           // ldmatrix row within 16
    const int lcol16 = (lane >> 4) * 16;    // ldmatrix 16B col select

    const int zo = blockIdx.z / zdiv, zi = blockIdx.z % zdiv;
    Ahi += zo*sAo + zi*sAi;  Alo += zo*sAo + zi*sAi;
    Bhi += zo*sBo + zi*sBi;  Blo += zo*sBo + zi*sBi;
    const ll coff = zo*sCo + zi*sCi;

    const int m0 = blockIdx.y * 128;
    const int n0 = blockIdx.x * 128;
    const int NK = K / KC;

    // cp.async loader mapping: 2 threads per row, 4x16B each
    const int lrow = tid >> 1;
    const int lseg0 = (tid & 1) * 4;

    auto fetch_stage = [&](int s){
        const u32 base = stage0 + (s % PIPE) * STAGE_BYTES;
        const int k0 = s * KC;
        #pragma unroll
        for (int t4 = 0; t4 < 4; t4++) {
            const __nv_bfloat16* src = (t4==0)?Ahi:(t4==1)?Alo:(t4==2)?Bhi:Blo;
            const int ld  = (t4 < 2) ? lda : ldb;
            const int r0  = (t4 < 2) ? m0  : n0;
            const __nv_bfloat16* gp = src + (ll)(r0 + lrow)*ld + k0 + lseg0*8;
            const u32 dbase = base + t4 * TILE_BYTES;
            #pragma unroll
            for (int j = 0; j < 4; j++) {
                u32 doff = SWZ((u32)(lrow*128 + (lseg0 + j)*16));
                cpa16(dbase + doff, gp + j*8);
            }
        }
        cpc();
    };

    float acc[4][4][4];
    #pragma unroll
    for (int i=0;i<4;i++)
    #pragma unroll
    for (int j=0;j<4;j++)
    #pragma unroll
    for (int r=0;r<4;r++) acc[i][j][r] = 0.f;

    int fetched = 0;
    for (; fetched < PIPE-1 && fetched < NK; fetched++) fetch_stage(fetched);

    for (int kc = 0; kc < NK; kc++) {
        const int pend = fetched - kc - 1;
        if (pend <= 0) cpw<0>(); else if (pend == 1) cpw<1>(); else cpw<2>();
        __syncthreads();

        const u32 sb  = stage0 + (kc % PIPE) * STAGE_BYTES;
        const u32 sAh = sb, sAl = sb + TILE_BYTES;
        const u32 sBh = sb + 2*TILE_BYTES, sBl = sb + 3*TILE_BYTES;

        #pragma unroll
        for (int k16 = 0; k16 < 4; k16++) {
            u32 ah[4][4], al[4][4], bh[2][4], bl[2][4];
            #pragma unroll
            for (int mf = 0; mf < 4; mf++) {
                u32 off = SWZ((u32)((wm + mf*16 + lrow16)*128 + k16*32 + lcol16));
                ldm4(ah[mf], sAh + off);
                ldm4(al[mf], sAl + off);
            }
            #pragma unroll
            for (int nf2 = 0; nf2 < 2; nf2++) {
                u32 off = SWZ((u32)((wn + nf2*16 + lrow16)*128 + k16*32 + lcol16));
                ldm4(bh[nf2], sBh + off);
                ldm4(bl[nf2], sBl + off);
            }
            #pragma unroll
            for (int mf = 0; mf < 4; mf++)
            #pragma unroll
            for (int nf = 0; nf < 4; nf++) {
                const int n2 = nf >> 1, od = nf & 1;
                mma16816(acc[mf][nf], ah[mf], bh[n2][od], bh[n2][od+2]);
                mma16816(acc[mf][nf], ah[mf], bl[n2][od], bl[n2][od+2]);
                mma16816(acc[mf][nf], al[mf], bh[n2][od], bh[n2][od+2]);
            }
        }
        __syncthreads();
        if (fetched < NK) { fetch_stage(fetched); fetched++; }
    }

    // epilogue
    const int g = lane >> 2, tig = lane & 3;
    #pragma unroll
    for (int mf = 0; mf < 4; mf++) {
        #pragma unroll
        for (int nf = 0; nf < 4; nf++) {
            const ll m = m0 + wm + mf*16 + g;
            const int n = n0 + wn + nf*8 + tig*2;
            float d0 = acc[mf][nf][0]*alpha, d1 = acc[mf][nf][1]*alpha;
            float d2 = acc[mf][nf][2]*alpha, d3 = acc[mf][nf][3]*alpha;
            if (EPI == 0) {
                float2 v01 = {d0, d1}, v23 = {d2, d3};
                *reinterpret_cast<float2*>(Cf + coff + m*ldc + n) = v01;
                *reinterpret_cast<float2*>(Cf + coff + (m+8)*ldc + n) = v23;
            } else {
                __nv_bfloat16 h0,l0,h1,l1,h2,l2,h3,l3;
                bsplit(d0,h0,l0); bsplit(d1,h1,l1); bsplit(d2,h2,l2); bsplit(d3,h3,l3);
                __nv_bfloat162 hh01; hh01.x=h0; hh01.y=h1;
                __nv_bfloat162 ll01; ll01.x=l0; ll01.y=l1;
                __nv_bfloat162 hh23; hh23.x=h2; hh23.y=h3;
                __nv_bfloat162 ll23; ll23.x=l2; ll23.y=l3;
                *reinterpret_cast<u32*>(Chi + coff + m*ldc + n) = *reinterpret_cast<u32*>(&hh01);
                *reinterpret_cast<u32*>(Clo + coff + m*ldc + n) = *reinterpret_cast<u32*>(&ll01);
                *reinterpret_cast<u32*>(Chi + coff + (m+8)*ldc + n) = *reinterpret_cast<u32*>(&hh23);
                *reinterpret_cast<u32*>(Clo + coff + (m+8)*ldc + n) = *reinterpret_cast<u32*>(&ll23);
            }
        }
    }
}

// --------------------------- prep kernels ----------------------------------
__global__ __launch_bounds__(256)
void split_x_kernel(const float* __restrict__ x, __nv_bfloat16* __restrict__ hi,
                    __nv_bfloat16* __restrict__ lo)
{
    const ll i = (ll)blockIdx.x * 256 + threadIdx.x;
    float v = x[i];
    __nv_bfloat16 h, l; bsplit(v, h, l);
    hi[i] = h; lo[i] = l;
}

// in [R,C] f32 -> out [C,R] split bf16
__global__ __launch_bounds__(256)
void transpose_split_kernel(const float* __restrict__ in, __nv_bfloat16* __restrict__ ohi,
                            __nv_bfloat16* __restrict__ olo, int R, int C)
{
    __shared__ float t[32][33];
    const int c0 = blockIdx.x * 32, r0 = blockIdx.y * 32;
    const int tx = threadIdx.x, ty = threadIdx.y;
    #pragma unroll
    for (int i = 0; i < 4; i++)
        t[ty + 8*i][tx] = in[(ll)(r0 + ty + 8*i) * C + c0 + tx];
    __syncthreads();
    #pragma unroll
    for (int i = 0; i < 4; i++) {
        float v = t[tx][ty + 8*i];
        __nv_bfloat16 h, l; bsplit(v, h, l);
        const ll o = (ll)(c0 + ty + 8*i) * R + r0 + tx;
        ohi[o] = h; olo[o] = l;
    }
}

// --------------------------- softmax stats ---------------------------------
__global__ __launch_bounds__(256)
void softmax_stats_kernel(const float* __restrict__ S, float* __restrict__ rowmax,
                          float* __restrict__ rowinv)
{
    const ll row = blockIdx.x;
    const float* p = S + row * SEQ;
    const int tid = threadIdx.x;
    float v[8];
    float m = -1e30f;
    #pragma unroll
    for (int i = 0; i < 8; i++) { v[i] = p[tid + 256*i]; m = fmaxf(m, v[i]); }
    #pragma unroll
    for (int o = 16; o; o >>= 1) m = fmaxf(m, __shfl_xor_sync(0xffffffffu, m, o));
    __shared__ float sm[8], ssum[8];
    if ((tid & 31) == 0) sm[tid >> 5] = m;
    __syncthreads();
    float bm = fmaxf(fmaxf(fmaxf(sm[0],sm[1]),fmaxf(sm[2],sm[3])),
                     fmaxf(fmaxf(sm[4],sm[5]),fmaxf(sm[6],sm[7])));
    float s = 0.f;
    #pragma unroll
    for (int i = 0; i < 8; i++) s += __expf(v[i] - bm);
    #pragma unroll
    for (int o = 16; o; o >>= 1) s += __shfl_xor_sync(0xffffffffu, s, o);
    if ((tid & 31) == 0) ssum[tid >> 5] = s;
    __syncthreads();
    if (tid == 0) {
        float tot = ssum[0]+ssum[1]+ssum[2]+ssum[3]+ssum[4]+ssum[5]+ssum[6]+ssum[7];
        rowmax[row] = bm;
        rowinv[row] = 1.0f / tot;
    }
}

// colsum with q-split + atomics: grid (k_chunks, bh, q_chunks)
__global__ __launch_bounds__(256)
void colsum2_kernel(const float* __restrict__ S, const float* __restrict__ rowmax,
                    const float* __restrict__ rowinv, float* __restrict__ colsum)
{
    const int bh = blockIdx.y;
    const int k  = blockIdx.x * 256 + threadIdx.x;
    const int q0 = blockIdx.z * 128;
    const float* sp = S + (ll)bh*SEQ*SEQ + (ll)q0*SEQ + k;
    const float* mp = rowmax + bh*SEQ + q0;
    const float* ip = rowinv + bh*SEQ + q0;
    float acc = 0.f;
    #pragma unroll 4
    for (int q = 0; q < 128; q++)
        acc += __expf(sp[(ll)q*SEQ] - __ldg(&mp[q])) * __ldg(&ip[q]);
    atomicAdd(&colsum[bh*SEQ + k], acc);
}

// vals = v * colsum, re-split to bf16 hi/lo
__global__ __launch_bounds__(256)
void scale_v_split_kernel(const __nv_bfloat16* __restrict__ qhi, const __nv_bfloat16* __restrict__ qlo,
                          const float* __restrict__ colsum,
                          __nv_bfloat16* __restrict__ vhi, __nv_bfloat16* __restrict__ vlo)
{
    const ll idx = (ll)blockIdx.x * 256 + threadIdx.x;
    const int col = (int)(idx & (HDIM - 1));
    const int row = (int)(idx >> 11);
    const int h = col >> 7;
    const int b = row >> 11;
    const int s = row & (SEQ - 1);
    const ll qo = (ll)row * QN + 2*NH*DHEAD + col;
    float v = __bfloat162float(qhi[qo]) + __bfloat162float(qlo[qo]);
    v *= colsum[(b*NH + h)*SEQ + s];
    __nv_bfloat16 h16, l16; bsplit(v, h16, l16);
    vhi[idx] = h16; vlo[idx] = l16;
}

// ---------------------------------------------------------------------------
extern "C" void kernel_launch(void* const* d_in, const int* in_sizes, int n_in,
                              void* d_out, int out_size)
{
    const float* x     = (const float*)d_in[0];
    const float* w_qkv = (const float*)d_in[1];
    const float* w_o   = (const float*)d_in[2];
    float* out = (float*)d_out;

    __nv_bfloat16 *xhi,*xlo,*wqh,*wql,*woh,*wol,*qh,*qlp,*vh,*vl;
    float *scores,*rowmax,*rowinv,*colsum;
    cudaGetSymbolAddress((void**)&xhi, g_xhi);   cudaGetSymbolAddress((void**)&xlo, g_xlo);
    cudaGetSymbolAddress((void**)&wqh, g_wqT_hi); cudaGetSymbolAddress((void**)&wql, g_wqT_lo);
    cudaGetSymbolAddress((void**)&woh, g_woT_hi); cudaGetSymbolAddress((void**)&wol, g_woT_lo);
    cudaGetSymbolAddress((void**)&qh,  g_qkv_hi); cudaGetSymbolAddress((void**)&qlp, g_qkv_lo);
    cudaGetSymbolAddress((void**)&vh,  g_vhi);    cudaGetSymbolAddress((void**)&vl,  g_vlo);
    cudaGetSymbolAddress((void**)&scores, g_scores);
    cudaGetSymbolAddress((void**)&rowmax, g_rowmax);
    cudaGetSymbolAddress((void**)&rowinv, g_rowinv);
    cudaGetSymbolAddress((void**)&colsum, g_colsum);

    cudaFuncSetAttribute(gemm_mma<0>, cudaFuncAttributeMaxDynamicSharedMemorySize, GSMEM_SZ);
    cudaFuncSetAttribute(gemm_mma<1>, cudaFuncAttributeMaxDynamicSharedMemorySize, GSMEM_SZ);

    // prep: split/transpose inputs
    split_x_kernel<<<(MR*HDIM)/256, 256>>>(x, xhi, xlo);
    transpose_split_kernel<<<dim3(QN/32, HDIM/32), dim3(32,8)>>>(w_qkv, wqh, wql, HDIM, QN);
    transpose_split_kernel<<<dim3(HDIM/32, HDIM/32), dim3(32,8)>>>(w_o, woh, wol, HDIM, HDIM);

    // 1) qkv = x @ w_qkv  (split bf16 out)
    gemm_mma<1><<<dim3(QN/128, MR/128, 1), 256, GSMEM_SZ>>>(
        xhi, xlo, wqh, wql, nullptr, qh, qlp,
        HDIM, HDIM, HDIM, QN, 1, 0,0,0,0,0,0, 1.0f);

    // 2) scores = (Q @ K^T)/sqrt(128), z = b*16+h
    gemm_mma<0><<<dim3(SEQ/128, SEQ/128, NBH), 256, GSMEM_SZ>>>(
        qh, qlp, qh + NH*DHEAD, qlp + NH*DHEAD, scores, nullptr, nullptr,
        DHEAD, QN, QN, SEQ, NH,
        (ll)SEQ*QN, 128, (ll)SEQ*QN, 128,
        (ll)NH*SEQ*SEQ, (ll)SEQ*SEQ, 0.08838834764831845f);

    // 3) per-row softmax stats
    softmax_stats_kernel<<<NBH*SEQ, 256>>>(scores, rowmax, rowinv);

    // 4) colsum over q (atomic, q-split)
    cudaMemsetAsync(colsum, 0, NBH*SEQ*sizeof(float));
    colsum2_kernel<<<dim3(SEQ/256, NBH, SEQ/128), 256>>>(scores, rowmax, rowinv, colsum);

    // 5) vals = v * colsum, split
    scale_v_split_kernel<<<(MR*HDIM)/256, 256>>>(qh, qlp, colsum, vh, vl);

    // 6) out = vals @ w_o
    gemm_mma<0><<<dim3(HDIM/128, MR/128, 1), 256, GSMEM_SZ>>>(
        vh, vl, woh, wol, out, nullptr, nullptr,
        HDIM, HDIM, HDIM, HDIM, 1, 0,0,0,0,0,0, 1.0f);
}